// round 15
// baseline (speedup 1.0000x reference)
#include <cuda_runtime.h>
#include <cstdint>

// 3-level Haar DWT, fully fused: 8 inputs/thread, single 256-bit load.
// x: [B, L=16384] fp32. Output concat: [cA3 (B*2048) | cD3 (B*2048) | cD2 (B*4096) | cD1 (B*8192)]
//
// Per thread t (0 .. B*2048-1), inputs [8t, 8t+8):
//   load  : 1x ld.global.v8.f32  (32B per lane, warp = 1KB in one instruction)
//   stores: cD1 STG.128, cD2 STG.64, cD3/cA3 STG.32 — all coalesced, default policy.
// Low register count (~26) -> 8 CTAs/SM, combining R14's v8 efficiency with
// R10's occupancy/latency hiding.

__global__ __launch_bounds__(256) void haar3_v8_8(
    const float* __restrict__ in,     // B*16384
    float*  __restrict__ cA3,         // B*2048
    float*  __restrict__ cD3,         // B*2048
    float2* __restrict__ cD2_2,       // B*4096 floats
    float4* __restrict__ cD1_4,       // B*8192 floats
    int total)                        // B * 2048
{
    int t = blockIdx.x * blockDim.x + threadIdx.x;
    if (t >= total) return;

    const float S  = 0.70710678118654752440f;   // 2^-1/2
    const float S2 = 0.5f;
    const float S3 = 0.35355339059327376220f;   // 2^-3/2

    const float* p = in + (size_t)t * 8;

    float x0,x1,x2,x3,x4,x5,x6,x7;
    asm volatile("ld.global.v8.f32 {%0,%1,%2,%3,%4,%5,%6,%7}, [%8];"
        : "=f"(x0),"=f"(x1),"=f"(x2),"=f"(x3),
          "=f"(x4),"=f"(x5),"=f"(x6),"=f"(x7)
        : "l"(p));

    // ---- level 1: 4 pair sums / diffs ----
    float a0 = x0 + x1, d0 = x0 - x1;
    float a1 = x2 + x3, d1 = x2 - x3;
    float a2 = x4 + x5, d2 = x4 - x5;
    float a3 = x6 + x7, d3 = x6 - x7;

    // ---- level 2 ----
    float A0 = a0 + a1, D0 = a0 - a1;
    float A1 = a2 + a3, D1 = a2 - a3;

    // ---- level 3 ----
    float ca3 = S3 * (A0 + A1);
    float cd3 = S3 * (A0 - A1);

    // ---- stores (all coalesced, default policy) ----
    cD1_4[t] = make_float4(S * d0, S * d1, S * d2, S * d3);
    cD2_2[t] = make_float2(S2 * D0, S2 * D1);
    cD3[t]   = cd3;
    cA3[t]   = ca3;
}

extern "C" void kernel_launch(void* const* d_in, const int* in_sizes, int n_in,
                              void* d_out, int out_size)
{
    const float* x = (const float*)d_in[0];
    float* out = (float*)d_out;

    const int L = 16384;
    const int B = in_sizes[0] / L;      // 2048
    const int total = B * (L / 8);      // B * 2048

    // Output layout: [cA3 | cD3 | cD2 | cD1]
    float*  cA3 = out;
    float*  cD3 = out + (size_t)B * (L / 8);                 // + B*2048
    float2* cD2 = (float2*)(out + (size_t)2 * B * (L / 8));  // + B*4096
    float4* cD1 = (float4*)(out + (size_t)B * (L / 2));      // + B*8192

    int threads = 256;
    int blocks = (total + threads - 1) / threads;
    haar3_v8_8<<<blocks, threads>>>(x, cA3, cD3, cD2, cD1, total);
}